// round 15
// baseline (speedup 1.0000x reference)
#include <cuda_runtime.h>
#include <cuda_fp16.h>
#include <cstdint>

// Problem constants
#define B_   8
#define N1_  8192
#define N2_  2048
#define C1_  128
#define C2_  256
#define H_   256
#define CIN_ 384   // C2 + C1

// ---------------- device scratch (no allocations allowed) ----------------
__device__ float  g_feat2t[B_ * N2_ * C2_];     // [B][N2][C2] fp32
__device__ float4 g_x2p[B_ * N2_];              // packed {x,y,z,|x|^2}
__device__ int    g_idx[B_ * N1_ * 3];
__device__ float  g_w  [B_ * N1_ * 3];
__device__ float  g_pd [B_ * N1_ * 4 * 3];      // partial top-3 dists
__device__ int    g_pi [B_ * N1_ * 4 * 3];      // partial top-3 indices
__device__ __half g_xcat[B_ * N1_ * CIN_];      // [B][N1][384] fp16 row-major
__device__ __half g_A1h[H_ * CIN_];             // W1 fp16 row-major [n][k]
__device__ float  g_c1[H_];
__device__ __half g_A2h[H_ * H_];               // W2 fp16 row-major [n][k]
__device__ float  g_c2[H_];

// ---------------- small PTX helpers ----------------------------------------
__device__ __forceinline__ uint32_t smem_u32(const void* p) {
    uint32_t a;
    asm("{ .reg .u64 t; cvta.to.shared.u64 t, %1; cvt.u32.u64 %0, t; }" : "=r"(a) : "l"(p));
    return a;
}
__device__ __forceinline__ void cpa16(uint32_t dst, const void* src) {
    asm volatile("cp.async.cg.shared.global [%0], [%1], 16;" :: "r"(dst), "l"(src));
}
#define CP_COMMIT()  asm volatile("cp.async.commit_group;")
#define CP_WAIT1()   asm volatile("cp.async.wait_group 1;")
#define CP_WAIT0()   asm volatile("cp.async.wait_group 0;")

// m16n8k16 fp16 MMA, fp32 accum, D = A*B + D
__device__ __forceinline__ void mma_f16(float* c, const uint32_t* a,
                                        uint32_t b0, uint32_t b1) {
    asm volatile(
        "mma.sync.aligned.m16n8k16.row.col.f32.f16.f16.f32 "
        "{%0,%1,%2,%3}, {%4,%5,%6,%7}, {%8,%9}, {%0,%1,%2,%3};"
        : "+f"(c[0]), "+f"(c[1]), "+f"(c[2]), "+f"(c[3])
        : "r"(a[0]), "r"(a[1]), "r"(a[2]), "r"(a[3]), "r"(b0), "r"(b1));
}
__device__ __forceinline__ void ldsm_x4(uint32_t& r0, uint32_t& r1,
                                        uint32_t& r2, uint32_t& r3, uint32_t addr) {
    asm volatile("ldmatrix.sync.aligned.m8n8.x4.shared.b16 {%0,%1,%2,%3}, [%4];"
        : "=r"(r0), "=r"(r1), "=r"(r2), "=r"(r3) : "r"(addr));
}
__device__ __forceinline__ uint32_t pack_h2(float lo, float hi) {
    __half2 h = __floats2half2_rn(lo, hi);
    return *(uint32_t*)&h;
}

// ---------------- 1) transpose features2 [B][C2][N2] -> [B][N2][C2] --------
__global__ void transpose_f2_kernel(const float* __restrict__ f2) {
    __shared__ float tile[32][33];
    int b  = blockIdx.z;
    int c0 = blockIdx.y * 32;
    int n0 = blockIdx.x * 32;
    int tx = threadIdx.x, ty = threadIdx.y;
    const float* src = f2 + (size_t)b * C2_ * N2_;
#pragma unroll
    for (int i = 0; i < 32; i += 8)
        tile[ty + i][tx] = src[(size_t)(c0 + ty + i) * N2_ + n0 + tx];
    __syncthreads();
    float* dst = g_feat2t + (size_t)b * N2_ * C2_;
#pragma unroll
    for (int i = 0; i < 32; i += 8)
        dst[(size_t)(n0 + ty + i) * C2_ + c0 + tx] = tile[tx][ty + i];
}

// ---------------- 2) setup: pack xyz2 + fold BN -> fp16 row-major W --------
__global__ void setup_kernel(const float* __restrict__ xyz2,
                             const float* __restrict__ w1, const float* __restrict__ b1,
                             const float* __restrict__ g1, const float* __restrict__ be1,
                             const float* __restrict__ m1, const float* __restrict__ v1,
                             const float* __restrict__ w2, const float* __restrict__ b2,
                             const float* __restrict__ g2, const float* __restrict__ be2,
                             const float* __restrict__ m2, const float* __restrict__ v2) {
    int blk = blockIdx.x;
    int t = threadIdx.x;
    if (blk < 64) {                       // pack xyz2
        int b = blk >> 3;
        int i = (blk & 7) * 256 + t;
        const float* x2 = xyz2 + (size_t)b * 3 * N2_;
        float X = x2[i], Y = x2[N2_ + i], Z = x2[2 * N2_ + i];
        g_x2p[b * N2_ + i] = make_float4(X, Y, Z, X * X + Y * Y + Z * Z);
    } else {
        int tid2 = (blk - 64) * 256 + t;
        if (tid2 < H_) {
            float s1 = g1[tid2] * rsqrtf(v1[tid2] + 1e-5f);
            g_c1[tid2] = (b1[tid2] - m1[tid2]) * s1 + be1[tid2];
            float s2 = g2[tid2] * rsqrtf(v2[tid2] + 1e-5f);
            g_c2[tid2] = (b2[tid2] - m2[tid2]) * s2 + be2[tid2];
        }
        for (int j = tid2; j < H_ * CIN_; j += 8192) {
            int n = j / CIN_;
            float s = g1[n] * rsqrtf(v1[n] + 1e-5f);
            g_A1h[j] = __float2half_rn(w1[j] * s);
        }
        for (int j = tid2; j < H_ * H_; j += 8192) {
            int n = j / H_;
            float s = g2[n] * rsqrtf(v2[n] + 1e-5f);
            g_A2h[j] = __float2half_rn(w2[j] * s);
        }
    }
}

// ---------------- 3) kNN partial: quarter of N2, 2 points/thread -----------
#define QN_ (N2_ / 4)   // 512
__global__ void __launch_bounds__(128)
knn_part_kernel(const float* __restrict__ xyz1) {
    __shared__ float4 s2[QN_];
    int b  = blockIdx.z;
    int q  = blockIdx.y;
    int n0 = blockIdx.x * 256;
    int t  = threadIdx.x;

    const float4* src = g_x2p + b * N2_ + q * QN_;
    for (int i = t; i < QN_; i += 128) s2[i] = src[i];
    __syncthreads();

    const float* x1 = xyz1 + (size_t)b * 3 * N1_;
    int na = n0 + t, nb = n0 + 128 + t;
    float ax = x1[na], ay = x1[N1_ + na], az = x1[2 * N1_ + na];
    float bx = x1[nb], by = x1[N1_ + nb], bz = x1[2 * N1_ + nb];

    float ad0 = 3.4e38f, ad1 = 3.4e38f, ad2 = 3.4e38f;
    float bd0 = 3.4e38f, bd1 = 3.4e38f, bd2 = 3.4e38f;
    int ai0 = 0, ai1 = 0, ai2 = 0, bi0 = 0, bi1 = 0, bi2 = 0;

#pragma unroll 4
    for (int j = 0; j < QN_; j++) {
        float4 p = s2[j];
        float ta = ax * p.x; ta = fmaf(ay, p.y, ta); ta = fmaf(az, p.z, ta);
        float da = fmaf(-2.0f, ta, p.w);
        float tb = bx * p.x; tb = fmaf(by, p.y, tb); tb = fmaf(bz, p.z, tb);
        float db = fmaf(-2.0f, tb, p.w);
        if (da < ad2) {
            if (da < ad1) {
                if (da < ad0) { ad2 = ad1; ai2 = ai1; ad1 = ad0; ai1 = ai0; ad0 = da; ai0 = j; }
                else          { ad2 = ad1; ai2 = ai1; ad1 = da;  ai1 = j; }
            } else            { ad2 = da;  ai2 = j; }
        }
        if (db < bd2) {
            if (db < bd1) {
                if (db < bd0) { bd2 = bd1; bi2 = bi1; bd1 = bd0; bi1 = bi0; bd0 = db; bi0 = j; }
                else          { bd2 = bd1; bi2 = bi1; bd1 = db;  bi1 = j; }
            } else            { bd2 = db;  bi2 = j; }
        }
    }
    int joff = q * QN_;
    size_t basea = ((size_t)(b * N1_ + na) * 4 + q) * 3;
    g_pd[basea + 0] = ad0; g_pd[basea + 1] = ad1; g_pd[basea + 2] = ad2;
    g_pi[basea + 0] = ai0 + joff; g_pi[basea + 1] = ai1 + joff; g_pi[basea + 2] = ai2 + joff;
    size_t baseb = ((size_t)(b * N1_ + nb) * 4 + q) * 3;
    g_pd[baseb + 0] = bd0; g_pd[baseb + 1] = bd1; g_pd[baseb + 2] = bd2;
    g_pi[baseb + 0] = bi0 + joff; g_pi[baseb + 1] = bi1 + joff; g_pi[baseb + 2] = bi2 + joff;
}

// ---------------- 4) merge 4 partial top-3 lists + weights -----------------
__global__ void knn_merge_kernel(const float* __restrict__ xyz1) {
    int gid = blockIdx.x * 256 + threadIdx.x;
    int b = gid >> 13;
    int n = gid & (N1_ - 1);

    float d0 = 3.4e38f, d1 = 3.4e38f, d2 = 3.4e38f;
    int   i0 = 0, i1 = 0, i2 = 0;
    size_t base = (size_t)gid * 12;
#pragma unroll
    for (int k = 0; k < 12; k++) {
        float d = g_pd[base + k];
        int   i = g_pi[base + k];
        if (d < d2) {
            if (d < d1) {
                if (d < d0) { d2 = d1; i2 = i1; d1 = d0; i1 = i0; d0 = d; i0 = i; }
                else        { d2 = d1; i2 = i1; d1 = d;  i1 = i; }
            } else          { d2 = d;  i2 = i; }
        }
    }
    const float* x1 = xyz1 + (size_t)b * 3 * N1_;
    float px = x1[n], py = x1[N1_ + n], pz = x1[2 * N1_ + n];
    float pn = px * px + py * py + pz * pz;
    d0 = fmaxf(d0 + pn, 1e-10f);
    d1 = fmaxf(d1 + pn, 1e-10f);
    d2 = fmaxf(d2 + pn, 1e-10f);
    float w0 = 1.0f / d0, w1 = 1.0f / d1, w2 = 1.0f / d2;
    float inv = 1.0f / (w0 + w1 + w2);
    size_t ob = (size_t)gid * 3;
    g_idx[ob + 0] = i0; g_idx[ob + 1] = i1; g_idx[ob + 2] = i2;
    g_w[ob + 0] = w0 * inv; g_w[ob + 1] = w1 * inv; g_w[ob + 2] = w2 * inv;
}

// ---------------- 5) interp (float2/half2) + skip transpose ----------------
__global__ void interp_skip_kernel(const float* __restrict__ f1) {
    __shared__ int   sidx[16 * 3];
    __shared__ float swt [16 * 3];
    __shared__ float tile[32][33];
    int blk = blockIdx.x;
    int t = threadIdx.x;
    if (blk < 4096) {
        int b  = blk >> 9;
        int n0 = (blk & 511) * 16;
        if (t < 48) {
            size_t base = ((size_t)(b * N1_ + n0)) * 3;
            sidx[t] = g_idx[base + t];
            swt[t]  = g_w[base + t];
        }
        __syncthreads();
        const float* f2 = g_feat2t + (size_t)b * N2_ * C2_;
        int pair = t & 127;
        int ph   = t >> 7;
        int cofs = pair * 2;
#pragma unroll
        for (int pi = 0; pi < 8; pi++) {
            int p = ph * 8 + pi;
            int j3 = p * 3;
            float w0 = swt[j3], w1 = swt[j3 + 1], w2 = swt[j3 + 2];
            float2 a = *(const float2*)(f2 + (size_t)sidx[j3]     * C2_ + cofs);
            float2 c = *(const float2*)(f2 + (size_t)sidx[j3 + 1] * C2_ + cofs);
            float2 e = *(const float2*)(f2 + (size_t)sidx[j3 + 2] * C2_ + cofs);
            float v0 = w0 * a.x + w1 * c.x + w2 * e.x;
            float v1 = w0 * a.y + w1 * c.y + w2 * e.y;
            *(__half2*)(g_xcat + ((size_t)(b * N1_ + n0 + p)) * CIN_ + cofs) =
                __floats2half2_rn(v0, v1);
        }
    } else {
        int r  = blk - 4096;
        int b  = r >> 10;
        int rem = r & 1023;
        int c0 = (rem >> 8) * 32;
        int n0 = (rem & 255) * 32;
        int tx = t & 31, ty = t >> 5;
        const float* src = f1 + (size_t)b * C1_ * N1_;
#pragma unroll
        for (int i = 0; i < 32; i += 8)
            tile[ty + i][tx] = src[(size_t)(c0 + ty + i) * N1_ + n0 + tx];
        __syncthreads();
        __half* dst = g_xcat + (size_t)b * N1_ * CIN_;
#pragma unroll
        for (int i = 0; i < 32; i += 8)
            dst[(size_t)(n0 + ty + i) * CIN_ + C2_ + c0 + tx] =
                __float2half_rn(tile[tx][ty + i]);
    }
}

// ---------------- 6) fused 2-layer MLP: ldmatrix + fp16 mma.sync -----------
// Block: 128 pts x 256 out-ch, 256 threads (8 warps: 2M x 4N, warp 64x64).
// SMEM bytes: A bufs 2x4096 [0,8192); B bufs 2x8192 [8192,24576);
//             yfrag (row-major y, stride 264 halves) [24576, 92160).
// All tiles row-major (32B rows); fragments via ldmatrix.x4.
#define ABUF_B    0
#define BBUF_B    8192
#define YF_B      24576
#define YSTRIDE   264                    // halves per row (pad vs 256)
#define MLP_SMEM  92160
#define KT1 (CIN_ / 16)   // 24
#define KT2 (H_ / 16)     // 16

__global__ void __launch_bounds__(256)
mlp_fused_kernel(float* __restrict__ out_final) {
    extern __shared__ uint32_t smem[];
    uint32_t sbase = smem_u32(smem);

    int tid  = threadIdx.x;
    int wid  = tid >> 5;
    int lane = tid & 31;
    int g    = lane >> 2;
    int t4   = lane & 3;

    int wm = wid & 1;            // 0..1  (M warps, 64 rows)
    int wn = wid >> 1;           // 0..3  (N warps, 64 cols)

    int bz = blockIdx.x >> 6;
    int m0 = (blockIdx.x & 63) * 128;

    const __half* Abase = g_xcat + ((size_t)(bz * N1_ + m0)) * CIN_;
    __half* yfh = (__half*)((char*)smem + YF_B);

    // ldmatrix lane-address components
    int a_row  = lane & 15;              // row within 16-row tile
    int a_kh   = (lane >> 4) * 16;       // k-half byte offset
    int b_row  = (lane & 7) + ((lane >> 4) << 3);   // row within 16-n group
    int b_kh   = ((lane >> 3) & 1) * 16;

    // staging geometry (flat row copies)
    int sm_row = tid >> 1;               // A: row 0..127
    int sm_c   = tid & 1;                // 16B chunk within 32B row

#define STAGE1(buf, kt) do {                                                   \
    uint32_t dA = sbase + ABUF_B + (buf) * 4096;                               \
    cpa16(dA + sm_row * 32 + sm_c * 16,                                        \
          Abase + (size_t)sm_row * CIN_ + (kt) * 16 + sm_c * 8);               \
    uint32_t dB = sbase + BBUF_B + (buf) * 8192;                               \
    cpa16(dB + sm_row * 32 + sm_c * 16,                                        \
          g_A1h + (size_t)sm_row * CIN_ + (kt) * 16 + sm_c * 8);               \
    cpa16(dB + (sm_row + 128) * 32 + sm_c * 16,                                \
          g_A1h + (size_t)(sm_row + 128) * CIN_ + (kt) * 16 + sm_c * 8);       \
    CP_COMMIT();                                                               \
} while (0)

#define STAGE2B(buf, kt) do {                                                  \
    uint32_t dB = sbase + BBUF_B + (buf) * 8192;                               \
    cpa16(dB + sm_row * 32 + sm_c * 16,                                        \
          g_A2h + (size_t)sm_row * H_ + (kt) * 16 + sm_c * 8);                 \
    cpa16(dB + (sm_row + 128) * 32 + sm_c * 16,                                \
          g_A2h + (size_t)(sm_row + 128) * H_ + (kt) * 16 + sm_c * 8);         \
    CP_COMMIT();                                                               \
} while (0)

    float acc[4][8][4] = {};

    // ================= phase 1: K = 384, 24 k16-tiles =================
    STAGE1(0, 0);
#pragma unroll 1
    for (int kt = 0; kt < KT1; kt++) {
        int cur = kt & 1;
        if (kt + 1 < KT1) { STAGE1(cur ^ 1, kt + 1); CP_WAIT1(); }
        else              { CP_WAIT0(); }
        __syncthreads();
        uint32_t As = sbase + ABUF_B + cur * 4096;
        uint32_t Bs = sbase + BBUF_B + cur * 8192;
        uint32_t a[4][4];
#pragma unroll
        for (int mi = 0; mi < 4; mi++)
            ldsm_x4(a[mi][0], a[mi][1], a[mi][2], a[mi][3],
                    As + (wm * 64 + mi * 16 + a_row) * 32 + a_kh);
#pragma unroll
        for (int np = 0; np < 4; np++) {
            uint32_t b0a, b1a, b0b, b1b;
            ldsm_x4(b0a, b1a, b0b, b1b,
                    Bs + (wn * 64 + np * 16 + b_row) * 32 + b_kh);
#pragma unroll
            for (int mi = 0; mi < 4; mi++) {
                mma_f16(acc[mi][np * 2],     a[mi], b0a, b1a);
                mma_f16(acc[mi][np * 2 + 1], a[mi], b0b, b1b);
            }
        }
        __syncthreads();
    }

    STAGE2B(0, 0);   // overlap W2 k-tile 0 with epilogue-1

    // ---- epilogue 1: bias+relu -> yfrag (row-major y, stride 264) ----
#pragma unroll
    for (int ni = 0; ni < 8; ni++) {
        int nch = wn * 64 + ni * 8 + 2 * t4;
        float bv0 = __ldg(&g_c1[nch]);
        float bv1 = __ldg(&g_c1[nch + 1]);
#pragma unroll
        for (int mi = 0; mi < 4; mi++) {
            int m = wm * 64 + mi * 16 + g;
            float c0 = fmaxf(acc[mi][ni][0] + bv0, 0.0f);
            float c1 = fmaxf(acc[mi][ni][1] + bv1, 0.0f);
            float c2 = fmaxf(acc[mi][ni][2] + bv0, 0.0f);
            float c3 = fmaxf(acc[mi][ni][3] + bv1, 0.0f);
            *(__half2*)(yfh + (size_t)m * YSTRIDE + nch)       = __floats2half2_rn(c0, c1);
            *(__half2*)(yfh + (size_t)(m + 8) * YSTRIDE + nch) = __floats2half2_rn(c2, c3);
        }
    }

    // re-zero accumulators
#pragma unroll
    for (int mi = 0; mi < 4; mi++)
#pragma unroll
        for (int ni = 0; ni < 8; ni++)
#pragma unroll
            for (int j = 0; j < 4; j++) acc[mi][ni][j] = 0.0f;

    __syncthreads();   // yfrag visible to all

    // ================= phase 2: K = 256, A resident in yfrag =================
#pragma unroll 1
    for (int kt = 0; kt < KT2; kt++) {
        int cur = kt & 1;
        if (kt + 1 < KT2) { STAGE2B(cur ^ 1, kt + 1); CP_WAIT1(); }
        else              { CP_WAIT0(); }
        __syncthreads();
        uint32_t Bs = sbase + BBUF_B + cur * 8192;
        uint32_t a[4][4];
#pragma unroll
        for (int mi = 0; mi < 4; mi++)
            ldsm_x4(a[mi][0], a[mi][1], a[mi][2], a[mi][3],
                    sbase + YF_B
                    + ((wm * 64 + mi * 16 + a_row) * YSTRIDE + kt * 16) * 2
                    + a_kh);
#pragma unroll
        for (int np = 0; np < 4; np++) {
            uint32_t b0a, b1a, b0b, b1b;
            ldsm_x4(b0a, b1a, b0b, b1b,
                    Bs + (wn * 64 + np * 16 + b_row) * 32 + b_kh);
#pragma unroll
            for (int mi = 0; mi < 4; mi++) {
                mma_f16(acc[mi][np * 2],     a[mi], b0a, b1a);
                mma_f16(acc[mi][np * 2 + 1], a[mi], b0b, b1b);
            }
        }
        __syncthreads();
    }

    // ---- epilogue 2: bias+relu -> out [B][H][N1] (coalesced along points) ----
    float* dst = out_final + (size_t)bz * H_ * N1_;
#pragma unroll
    for (int ni = 0; ni < 8; ni++) {
        int n = wn * 64 + ni * 8 + 2 * t4;
        float bv0 = __ldg(&g_c2[n]);
        float bv1 = __ldg(&g_c2[n + 1]);
#pragma unroll
        for (int mi = 0; mi < 4; mi++) {
            int m = m0 + wm * 64 + mi * 16 + g;
            float c0 = fmaxf(acc[mi][ni][0] + bv0, 0.0f);
            float c1 = fmaxf(acc[mi][ni][1] + bv1, 0.0f);
            float c2 = fmaxf(acc[mi][ni][2] + bv0, 0.0f);
            float c3 = fmaxf(acc[mi][ni][3] + bv1, 0.0f);
            dst[(size_t)n * N1_ + m]           = c0;
            dst[(size_t)(n + 1) * N1_ + m]     = c1;
            dst[(size_t)n * N1_ + m + 8]       = c2;
            dst[(size_t)(n + 1) * N1_ + m + 8] = c3;
        }
    }
}

// ---------------- launch ----------------------------------------------------
extern "C" void kernel_launch(void* const* d_in, const int* in_sizes, int n_in,
                              void* d_out, int out_size) {
    const float* xyz1      = (const float*)d_in[0];
    const float* xyz2      = (const float*)d_in[1];
    const float* features1 = (const float*)d_in[2];
    const float* features2 = (const float*)d_in[3];
    const float* w1 = (const float*)d_in[4];
    const float* b1 = (const float*)d_in[5];
    const float* g1 = (const float*)d_in[6];
    const float* be1 = (const float*)d_in[7];
    const float* m1 = (const float*)d_in[8];
    const float* v1 = (const float*)d_in[9];
    const float* w2 = (const float*)d_in[10];
    const float* b2 = (const float*)d_in[11];
    const float* g2 = (const float*)d_in[12];
    const float* be2 = (const float*)d_in[13];
    const float* m2 = (const float*)d_in[14];
    const float* v2 = (const float*)d_in[15];
    float* out = (float*)d_out;

    cudaFuncSetAttribute(mlp_fused_kernel,
                         cudaFuncAttributeMaxDynamicSharedMemorySize, MLP_SMEM);

    transpose_f2_kernel<<<dim3(N2_ / 32, C2_ / 32, B_), dim3(32, 8)>>>(features2);
    setup_kernel<<<96, 256>>>(xyz2, w1, b1, g1, be1, m1, v1,
                              w2, b2, g2, be2, m2, v2);
    knn_part_kernel<<<dim3(N1_ / 256, 4, B_), 128>>>(xyz1);
    knn_merge_kernel<<<(B_ * N1_) / 256, 256>>>(xyz1);
    interp_skip_kernel<<<4096 + 8192, 256>>>(features1);
    mlp_fused_kernel<<<512, 256, MLP_SMEM>>>(out);
}

// round 16
// speedup vs baseline: 1.0468x; 1.0468x over previous
#include <cuda_runtime.h>
#include <cuda_fp16.h>
#include <cstdint>

// Problem constants
#define B_   8
#define N1_  8192
#define N2_  2048
#define C1_  128
#define C2_  256
#define H_   256
#define CIN_ 384   // C2 + C1

// ---------------- device scratch (no allocations allowed) ----------------
__device__ float  g_feat2t[B_ * N2_ * C2_];     // [B][N2][C2] fp32
__device__ float4 g_x2p[B_ * N2_];              // packed {x,y,z,|x|^2}
__device__ int    g_idx[B_ * N1_ * 3];
__device__ float  g_w  [B_ * N1_ * 3];
__device__ float  g_pd [B_ * N1_ * 4 * 3];      // partial top-3 dists
__device__ int    g_pi [B_ * N1_ * 4 * 3];      // partial top-3 indices
__device__ __half g_xcat[B_ * N1_ * CIN_];      // [B][N1][384] fp16 row-major
__device__ __half g_A1h[H_ * CIN_];             // W1 in B-frag image
__device__ float  g_c1[H_];
__device__ __half g_A2h[H_ * H_];               // W2 in B-frag image
__device__ float  g_c2[H_];

// ---------------- small PTX helpers ----------------------------------------
__device__ __forceinline__ uint32_t smem_u32(const void* p) {
    uint32_t a;
    asm("{ .reg .u64 t; cvta.to.shared.u64 t, %1; cvt.u32.u64 %0, t; }" : "=r"(a) : "l"(p));
    return a;
}
__device__ __forceinline__ void cpa16(uint32_t dst, const void* src) {
    asm volatile("cp.async.cg.shared.global [%0], [%1], 16;" :: "r"(dst), "l"(src));
}
#define CP_COMMIT()  asm volatile("cp.async.commit_group;")
#define CP_WAIT1()   asm volatile("cp.async.wait_group 1;")
#define CP_WAIT0()   asm volatile("cp.async.wait_group 0;")

// m16n8k16 fp16 MMA, fp32 accum, D = A*B + D
__device__ __forceinline__ void mma_f16(float* c, const uint32_t* a,
                                        uint32_t b0, uint32_t b1) {
    asm volatile(
        "mma.sync.aligned.m16n8k16.row.col.f32.f16.f16.f32 "
        "{%0,%1,%2,%3}, {%4,%5,%6,%7}, {%8,%9}, {%0,%1,%2,%3};"
        : "+f"(c[0]), "+f"(c[1]), "+f"(c[2]), "+f"(c[3])
        : "r"(a[0]), "r"(a[1]), "r"(a[2]), "r"(a[3]), "r"(b0), "r"(b1));
}
__device__ __forceinline__ uint32_t pack_h2(float lo, float hi) {
    __half2 h = __floats2half2_rn(lo, hi);
    return *(uint32_t*)&h;
}

// ---------------- 1) transpose features2 [B][C2][N2] -> [B][N2][C2] --------
__global__ void transpose_f2_kernel(const float* __restrict__ f2) {
    __shared__ float tile[32][33];
    int b  = blockIdx.z;
    int c0 = blockIdx.y * 32;
    int n0 = blockIdx.x * 32;
    int tx = threadIdx.x, ty = threadIdx.y;
    const float* src = f2 + (size_t)b * C2_ * N2_;
#pragma unroll
    for (int i = 0; i < 32; i += 8)
        tile[ty + i][tx] = src[(size_t)(c0 + ty + i) * N2_ + n0 + tx];
    __syncthreads();
    float* dst = g_feat2t + (size_t)b * N2_ * C2_;
#pragma unroll
    for (int i = 0; i < 32; i += 8)
        dst[(size_t)(n0 + ty + i) * C2_ + c0 + tx] = tile[tx][ty + i];
}

// ---------------- 2) setup: pack xyz2 + fold BN -> W B-frag images ---------
__global__ void setup_kernel(const float* __restrict__ xyz2,
                             const float* __restrict__ w1, const float* __restrict__ b1,
                             const float* __restrict__ g1, const float* __restrict__ be1,
                             const float* __restrict__ m1, const float* __restrict__ v1,
                             const float* __restrict__ w2, const float* __restrict__ b2,
                             const float* __restrict__ g2, const float* __restrict__ be2,
                             const float* __restrict__ m2, const float* __restrict__ v2) {
    int blk = blockIdx.x;
    int t = threadIdx.x;
    if (blk < 64) {                       // pack xyz2
        int b = blk >> 3;
        int i = (blk & 7) * 256 + t;
        const float* x2 = xyz2 + (size_t)b * 3 * N2_;
        float X = x2[i], Y = x2[N2_ + i], Z = x2[2 * N2_ + i];
        g_x2p[b * N2_ + i] = make_float4(X, Y, Z, X * X + Y * Y + Z * Z);
    } else {
        int tid2 = (blk - 64) * 256 + t;
        if (tid2 < H_) {
            float s1 = g1[tid2] * rsqrtf(v1[tid2] + 1e-5f);
            g_c1[tid2] = (b1[tid2] - m1[tid2]) * s1 + be1[tid2];
            float s2 = g2[tid2] * rsqrtf(v2[tid2] + 1e-5f);
            g_c2[tid2] = (b2[tid2] - m2[tid2]) * s2 + be2[tid2];
        }
        for (int j = tid2; j < H_ * CIN_; j += 8192) {
            int n = j / CIN_, k = j - n * CIN_;
            float s = g1[n] * rsqrtf(v1[n] + 1e-5f);
            int u32idx = ((k >> 4) * 32 + (n >> 3)) * 64
                       + ((n & 7) * 4 + ((k & 7) >> 1)) * 2 + ((k >> 3) & 1);
            g_A1h[u32idx * 2 + (k & 1)] = __float2half_rn(w1[j] * s);
        }
        for (int j = tid2; j < H_ * H_; j += 8192) {
            int n = j / H_, k = j - n * H_;
            float s = g2[n] * rsqrtf(v2[n] + 1e-5f);
            int u32idx = ((k >> 4) * 32 + (n >> 3)) * 64
                       + ((n & 7) * 4 + ((k & 7) >> 1)) * 2 + ((k >> 3) & 1);
            g_A2h[u32idx * 2 + (k & 1)] = __float2half_rn(w2[j] * s);
        }
    }
}

// ---------------- 3) kNN partial: quarter of N2, 2 points/thread -----------
#define QN_ (N2_ / 4)   // 512
__global__ void __launch_bounds__(128)
knn_part_kernel(const float* __restrict__ xyz1) {
    __shared__ float4 s2[QN_];
    int b  = blockIdx.z;
    int q  = blockIdx.y;
    int n0 = blockIdx.x * 256;
    int t  = threadIdx.x;

    const float4* src = g_x2p + b * N2_ + q * QN_;
    for (int i = t; i < QN_; i += 128) s2[i] = src[i];
    __syncthreads();

    const float* x1 = xyz1 + (size_t)b * 3 * N1_;
    int na = n0 + t, nb = n0 + 128 + t;
    float ax = x1[na], ay = x1[N1_ + na], az = x1[2 * N1_ + na];
    float bx = x1[nb], by = x1[N1_ + nb], bz = x1[2 * N1_ + nb];

    float ad0 = 3.4e38f, ad1 = 3.4e38f, ad2 = 3.4e38f;
    float bd0 = 3.4e38f, bd1 = 3.4e38f, bd2 = 3.4e38f;
    int ai0 = 0, ai1 = 0, ai2 = 0, bi0 = 0, bi1 = 0, bi2 = 0;

#pragma unroll 4
    for (int j = 0; j < QN_; j++) {
        float4 p = s2[j];
        float ta = ax * p.x; ta = fmaf(ay, p.y, ta); ta = fmaf(az, p.z, ta);
        float da = fmaf(-2.0f, ta, p.w);
        float tb = bx * p.x; tb = fmaf(by, p.y, tb); tb = fmaf(bz, p.z, tb);
        float db = fmaf(-2.0f, tb, p.w);
        if (da < ad2) {
            if (da < ad1) {
                if (da < ad0) { ad2 = ad1; ai2 = ai1; ad1 = ad0; ai1 = ai0; ad0 = da; ai0 = j; }
                else          { ad2 = ad1; ai2 = ai1; ad1 = da;  ai1 = j; }
            } else            { ad2 = da;  ai2 = j; }
        }
        if (db < bd2) {
            if (db < bd1) {
                if (db < bd0) { bd2 = bd1; bi2 = bi1; bd1 = bd0; bi1 = bi0; bd0 = db; bi0 = j; }
                else          { bd2 = bd1; bi2 = bi1; bd1 = db;  bi1 = j; }
            } else            { bd2 = db;  bi2 = j; }
        }
    }
    int joff = q * QN_;
    size_t basea = ((size_t)(b * N1_ + na) * 4 + q) * 3;
    g_pd[basea + 0] = ad0; g_pd[basea + 1] = ad1; g_pd[basea + 2] = ad2;
    g_pi[basea + 0] = ai0 + joff; g_pi[basea + 1] = ai1 + joff; g_pi[basea + 2] = ai2 + joff;
    size_t baseb = ((size_t)(b * N1_ + nb) * 4 + q) * 3;
    g_pd[baseb + 0] = bd0; g_pd[baseb + 1] = bd1; g_pd[baseb + 2] = bd2;
    g_pi[baseb + 0] = bi0 + joff; g_pi[baseb + 1] = bi1 + joff; g_pi[baseb + 2] = bi2 + joff;
}

// ---------------- 4) merge 4 partial top-3 lists + weights -----------------
__global__ void knn_merge_kernel(const float* __restrict__ xyz1) {
    int gid = blockIdx.x * 256 + threadIdx.x;
    int b = gid >> 13;
    int n = gid & (N1_ - 1);

    float d0 = 3.4e38f, d1 = 3.4e38f, d2 = 3.4e38f;
    int   i0 = 0, i1 = 0, i2 = 0;
    size_t base = (size_t)gid * 12;
#pragma unroll
    for (int k = 0; k < 12; k++) {
        float d = g_pd[base + k];
        int   i = g_pi[base + k];
        if (d < d2) {
            if (d < d1) {
                if (d < d0) { d2 = d1; i2 = i1; d1 = d0; i1 = i0; d0 = d; i0 = i; }
                else        { d2 = d1; i2 = i1; d1 = d;  i1 = i; }
            } else          { d2 = d;  i2 = i; }
        }
    }
    const float* x1 = xyz1 + (size_t)b * 3 * N1_;
    float px = x1[n], py = x1[N1_ + n], pz = x1[2 * N1_ + n];
    float pn = px * px + py * py + pz * pz;
    d0 = fmaxf(d0 + pn, 1e-10f);
    d1 = fmaxf(d1 + pn, 1e-10f);
    d2 = fmaxf(d2 + pn, 1e-10f);
    float w0 = 1.0f / d0, w1 = 1.0f / d1, w2 = 1.0f / d2;
    float inv = 1.0f / (w0 + w1 + w2);
    size_t ob = (size_t)gid * 3;
    g_idx[ob + 0] = i0; g_idx[ob + 1] = i1; g_idx[ob + 2] = i2;
    g_w[ob + 0] = w0 * inv; g_w[ob + 1] = w1 * inv; g_w[ob + 2] = w2 * inv;
}

// ---------------- 5) interp (float2/half2) + skip transpose ----------------
__global__ void interp_skip_kernel(const float* __restrict__ f1) {
    __shared__ int   sidx[16 * 3];
    __shared__ float swt [16 * 3];
    __shared__ float tile[32][33];
    int blk = blockIdx.x;
    int t = threadIdx.x;
    if (blk < 4096) {
        int b  = blk >> 9;
        int n0 = (blk & 511) * 16;
        if (t < 48) {
            size_t base = ((size_t)(b * N1_ + n0)) * 3;
            sidx[t] = g_idx[base + t];
            swt[t]  = g_w[base + t];
        }
        __syncthreads();
        const float* f2 = g_feat2t + (size_t)b * N2_ * C2_;
        int pair = t & 127;
        int ph   = t >> 7;
        int cofs = pair * 2;
#pragma unroll
        for (int pi = 0; pi < 8; pi++) {
            int p = ph * 8 + pi;
            int j3 = p * 3;
            float w0 = swt[j3], w1 = swt[j3 + 1], w2 = swt[j3 + 2];
            float2 a = *(const float2*)(f2 + (size_t)sidx[j3]     * C2_ + cofs);
            float2 c = *(const float2*)(f2 + (size_t)sidx[j3 + 1] * C2_ + cofs);
            float2 e = *(const float2*)(f2 + (size_t)sidx[j3 + 2] * C2_ + cofs);
            float v0 = w0 * a.x + w1 * c.x + w2 * e.x;
            float v1 = w0 * a.y + w1 * c.y + w2 * e.y;
            *(__half2*)(g_xcat + ((size_t)(b * N1_ + n0 + p)) * CIN_ + cofs) =
                __floats2half2_rn(v0, v1);
        }
    } else {
        int r  = blk - 4096;
        int b  = r >> 10;
        int rem = r & 1023;
        int c0 = (rem >> 8) * 32;
        int n0 = (rem & 255) * 32;
        int tx = t & 31, ty = t >> 5;
        const float* src = f1 + (size_t)b * C1_ * N1_;
#pragma unroll
        for (int i = 0; i < 32; i += 8)
            tile[ty + i][tx] = src[(size_t)(c0 + ty + i) * N1_ + n0 + tx];
        __syncthreads();
        __half* dst = g_xcat + (size_t)b * N1_ * CIN_;
#pragma unroll
        for (int i = 0; i < 32; i += 8)
            dst[(size_t)(n0 + ty + i) * CIN_ + C2_ + c0 + tx] =
                __float2half_rn(tile[tx][ty + i]);
    }
}

// ---------------- 6) fused 2-layer MLP: R12 staging + 3-stage ring ---------
// Block: 128 pts x 256 out-ch, 256 threads (8 warps: 2M x 4N, warp 64x64).
// SMEM u32: 3 ring bufs x 3072 (A 1024 + B 2048) [0, 9216);
//           yfrag [9216, 25600). Total 102400 bytes. One sync per k-tile.
#define YF_OFF   9216
#define MLP_SMEM 102400
#define KT1 (CIN_ / 16)   // 24
#define KT2 (H_ / 16)     // 16

__global__ void __launch_bounds__(256)
mlp_fused_kernel(float* __restrict__ out_final) {
    extern __shared__ uint32_t smem[];
    uint32_t sbase = smem_u32(smem);

    int tid  = threadIdx.x;
    int wid  = tid >> 5;
    int lane = tid & 31;
    int g    = lane >> 2;
    int t4   = lane & 3;

    int wm = wid & 1;            // 0..1  (M warps, 64 rows)
    int wn = wid >> 1;           // 0..3  (N warps, 64 cols)

    int bz = blockIdx.x >> 6;
    int m0 = (blockIdx.x & 63) * 128;

    const __half*   Abase = g_xcat + ((size_t)(bz * N1_ + m0)) * CIN_;
    const uint32_t* w1im  = (const uint32_t*)g_A1h;
    const uint32_t* w2im  = (const uint32_t*)g_A2h;
    uint32_t* yf = smem + YF_OFF;

#define STAGE1(kt) do { int _b = (kt) % 3;                                     \
    uint32_t dbase = sbase + _b * 12288;                                       \
    {                                                                          \
        int m = tid >> 1, c4 = tid & 1;                                        \
        int off = (((m >> 4) * 4) + 2 * c4 + ((m >> 3) & 1)) * 32 + (m & 7) * 4; \
        cpa16(dbase + off * 4, Abase + (size_t)m * CIN_ + (kt) * 16 + c4 * 8); \
    }                                                                          \
    uint32_t dB = dbase + 4096;                                                \
    cpa16(dB + tid * 16,         w1im + (kt) * 2048 + tid * 4);                \
    cpa16(dB + (tid + 256) * 16, w1im + (kt) * 2048 + (tid + 256) * 4);        \
    CP_COMMIT();                                                               \
} while (0)

#define STAGE2B(kt) do { int _b = (kt) % 3;                                    \
    uint32_t dB = sbase + _b * 12288 + 4096;                                   \
    cpa16(dB + tid * 16,         w2im + (kt) * 2048 + tid * 4);                \
    cpa16(dB + (tid + 256) * 16, w2im + (kt) * 2048 + (tid + 256) * 4);        \
    CP_COMMIT();                                                               \
} while (0)

    float acc[4][8][4] = {};

    // ================= phase 1: K = 384, 24 k16-tiles =================
    STAGE1(0);
    STAGE1(1);
#pragma unroll 1
    for (int kt = 0; kt < KT1; kt++) {
        if (kt < KT1 - 1) { CP_WAIT1(); } else { CP_WAIT0(); }
        __syncthreads();
        if (kt + 2 < KT1) STAGE1(kt + 2);
        const uint32_t* As = smem + (kt % 3) * 3072;
        const uint32_t* Bs = As + 1024;
        uint32_t a[4][4];
#pragma unroll
        for (int mi = 0; mi < 4; mi++) {
            const uint32_t* ap = As + ((wm * 4 + mi) * 4) * 32 + lane;
            a[mi][0] = ap[0];
            a[mi][1] = ap[32];
            a[mi][2] = ap[64];
            a[mi][3] = ap[96];
        }
#pragma unroll
        for (int ni = 0; ni < 8; ni++) {
            uint2 bv = *(const uint2*)(Bs + (wn * 8 + ni) * 64 + lane * 2);
#pragma unroll
            for (int mi = 0; mi < 4; mi++)
                mma_f16(acc[mi][ni], a[mi], bv.x, bv.y);
        }
    }

    // prestage W2 k-tiles 0,1 (all phase-1 groups retired; compute of last
    // two tiles done by the final WAIT0+sync above... last compute has no
    // trailing sync — add one before reusing buffers)
    __syncthreads();
    STAGE2B(0);
    STAGE2B(1);

    // ---- epilogue 1: bias+relu -> yfrag (phase-2 A-frag order, half2) ----
#pragma unroll
    for (int ni = 0; ni < 8; ni++) {
        int nch = wn * 64 + ni * 8 + 2 * t4;
        float bv0 = __ldg(&g_c1[nch]);
        float bv1 = __ldg(&g_c1[nch + 1]);
        int kt = wn * 4 + (ni >> 1);
        int rb = 2 * (ni & 1);
#pragma unroll
        for (int mi = 0; mi < 4; mi++) {
            int mt = wm * 4 + mi;
            float c0 = fmaxf(acc[mi][ni][0] + bv0, 0.0f);
            float c1 = fmaxf(acc[mi][ni][1] + bv1, 0.0f);
            float c2 = fmaxf(acc[mi][ni][2] + bv0, 0.0f);
            float c3 = fmaxf(acc[mi][ni][3] + bv1, 0.0f);
            yf[((mt * 16 + kt) * 4 + rb) * 32 + lane]     = pack_h2(c0, c1);
            yf[((mt * 16 + kt) * 4 + rb + 1) * 32 + lane] = pack_h2(c2, c3);
        }
    }

    // re-zero accumulators
#pragma unroll
    for (int mi = 0; mi < 4; mi++)
#pragma unroll
        for (int ni = 0; ni < 8; ni++)
#pragma unroll
            for (int j = 0; j < 4; j++) acc[mi][ni][j] = 0.0f;

    // ================= phase 2: K = 256, A resident in yfrag =================
#pragma unroll 1
    for (int kt = 0; kt < KT2; kt++) {
        if (kt < KT2 - 1) { CP_WAIT1(); } else { CP_WAIT0(); }
        __syncthreads();   // also covers yfrag visibility at kt=0
        if (kt + 2 < KT2) STAGE2B(kt + 2);
        const uint32_t* Bs = smem + (kt % 3) * 3072 + 1024;
        uint32_t a[4][4];
#pragma unroll
        for (int mi = 0; mi < 4; mi++) {
            const uint32_t* ap = yf + (((wm * 4 + mi) * 16 + kt) * 4) * 32 + lane;
            a[mi][0] = ap[0];
            a[mi][1] = ap[32];
            a[mi][2] = ap[64];
            a[mi][3] = ap[96];
        }
#pragma unroll
        for (int ni = 0; ni < 8; ni++) {
            uint2 bv = *(const uint2*)(Bs + (wn * 8 + ni) * 64 + lane * 2);
#pragma unroll
            for (int mi = 0; mi < 4; mi++)
                mma_f16(acc[mi][ni], a[mi], bv.x, bv.y);
        }
    }

    // ---- epilogue 2: bias+relu -> out [B][H][N1] (coalesced along points) ----
    float* dst = out_final + (size_t)bz * H_ * N1_;
#pragma unroll
    for (int ni = 0; ni < 8; ni++) {
        int n = wn * 64 + ni * 8 + 2 * t4;
        float bv0 = __ldg(&g_c2[n]);
        float bv1 = __ldg(&g_c2[n + 1]);
#pragma unroll
        for (int mi = 0; mi < 4; mi++) {
            int m = m0 + wm * 64 + mi * 16 + g;
            float c0 = fmaxf(acc[mi][ni][0] + bv0, 0.0f);
            float c1 = fmaxf(acc[mi][ni][1] + bv1, 0.0f);
            float c2 = fmaxf(acc[mi][ni][2] + bv0, 0.0f);
            float c3 = fmaxf(acc[mi][ni][3] + bv1, 0.0f);
            dst[(size_t)n * N1_ + m]           = c0;
            dst[(size_t)(n + 1) * N1_ + m]     = c1;
            dst[(size_t)n * N1_ + m + 8]       = c2;
            dst[(size_t)(n + 1) * N1_ + m + 8] = c3;
        }
    }
}

// ---------------- launch ----------------------------------------------------
extern "C" void kernel_launch(void* const* d_in, const int* in_sizes, int n_in,
                              void* d_out, int out_size) {
    const float* xyz1      = (const float*)d_in[0];
    const float* xyz2      = (const float*)d_in[1];
    const float* features1 = (const float*)d_in[2];
    const float* features2 = (const float*)d_in[3];
    const float* w1 = (const float*)d_in[4];
    const float* b1 = (const float*)d_in[5];
    const float* g1 = (const float*)d_in[6];
    const float* be1 = (const float*)d_in[7];
    const float* m1 = (const float*)d_in[8];
    const float* v1 = (const float*)d_in[9];
    const float* w2 = (const float*)d_in[10];
    const float* b2 = (const float*)d_in[11];
    const float* g2 = (const float*)d_in[12];
    const float* be2 = (const float*)d_in[13];
    const float* m2 = (const float*)d_in[14];
    const float* v2 = (const float*)d_in[15];
    float* out = (float*)d_out;

    cudaFuncSetAttribute(mlp_fused_kernel,
                         cudaFuncAttributeMaxDynamicSharedMemorySize, MLP_SMEM);

    transpose_f2_kernel<<<dim3(N2_ / 32, C2_ / 32, B_), dim3(32, 8)>>>(features2);
    setup_kernel<<<96, 256>>>(xyz2, w1, b1, g1, be1, m1, v1,
                              w2, b2, g2, be2, m2, v2);
    knn_part_kernel<<<dim3(N1_ / 256, 4, B_), 128>>>(xyz1);
    knn_merge_kernel<<<(B_ * N1_) / 256, 256>>>(xyz1);
    interp_skip_kernel<<<4096 + 8192, 256>>>(features1);
    mlp_fused_kernel<<<512, 256, MLP_SMEM>>>(out);
}